// round 6
// baseline (speedup 1.0000x reference)
#include <cuda_runtime.h>
#include <cuda_fp16.h>
#include <stdint.h>

#define N_NODES 100000
#define N_EDGES 3200000
#define F 128
#define T_POINTS 4

// ---- scratch (device globals; no allocations allowed) ----
__device__ __half g_support[(size_t)N_NODES * F];  // GEMM out / SPMM gather src (25.6 MB)
__device__ __half g_hh[(size_t)N_NODES * F];       // layer output fp16 -> next GEMM A (25.6 MB)
__device__ __half g_W1h[256 * 128];
__device__ __half g_W2h[128 * 128];
__device__ __half g_W3h[128 * 128];
__device__ int    g_rowptr[N_NODES + 1];
__device__ int    g_deg[N_NODES];
__device__ int    g_cursor[N_NODES];
__device__ uint2  g_csr[N_EDGES];                  // {src col, val bits} (25.6 MB)

// minimal type trait (avoid C-only builtins / header deps)
template <typename T> struct is_half_t { static const bool value = false; };
template <> struct is_half_t<__half>  { static const bool value = true;  };

// ---------------------------------------------------------------------------
// all three weight matrices fp32 -> fp16 in one launch (65536 halves total)
// ---------------------------------------------------------------------------
__global__ void __launch_bounds__(256, 1)
k_wconv(const float* __restrict__ W1, const float* __restrict__ W2,
        const float* __restrict__ W3,
        __half* __restrict__ W1h, __half* __restrict__ W2h, __half* __restrict__ W3h) {
    int i4 = (blockIdx.x * blockDim.x + threadIdx.x) * 4;
    const float* src; __half* dst; int off;
    if (i4 < 32768)       { src = W1; dst = W1h; off = i4; }
    else if (i4 < 49152)  { src = W2; dst = W2h; off = i4 - 32768; }
    else                  { src = W3; dst = W3h; off = i4 - 49152; }
    float4 v = *reinterpret_cast<const float4*>(&src[off]);
    __half2 p0 = __floats2half2_rn(v.x, v.y);
    __half2 p1 = __floats2half2_rn(v.z, v.w);
    uint2 packed;
    packed.x = *reinterpret_cast<uint32_t*>(&p0);
    packed.y = *reinterpret_cast<uint32_t*>(&p1);
    *reinterpret_cast<uint2*>(&dst[off]) = packed;
}

// ---------------------------------------------------------------------------
// CSR build: histogram -> single-block scan -> scatter
// ---------------------------------------------------------------------------
__global__ void __launch_bounds__(256, 1) k_zero_counts() {
    int i = blockIdx.x * blockDim.x + threadIdx.x;
    if (i < N_NODES) g_deg[i] = 0;
}

__global__ void __launch_bounds__(256, 1) k_hist(const int* __restrict__ ei) {
    int e = blockIdx.x * blockDim.x + threadIdx.x;
    if (e < N_EDGES) atomicAdd(&g_deg[ei[e]], 1);
}

__global__ void __launch_bounds__(1024, 1) k_scan() {
    __shared__ int sums[1024];
    const int tid = threadIdx.x;
    const int PER = (N_NODES + 1023) / 1024;
    const int base = tid * PER;
    int s = 0;
    #pragma unroll 1
    for (int i = 0; i < PER; i++) {
        int idx = base + i;
        if (idx < N_NODES) s += g_deg[idx];
    }
    sums[tid] = s;
    __syncthreads();
    #pragma unroll 1
    for (int off = 1; off < 1024; off <<= 1) {
        int v = (tid >= off) ? sums[tid - off] : 0;
        __syncthreads();
        sums[tid] += v;
        __syncthreads();
    }
    int run = (tid == 0) ? 0 : sums[tid - 1];
    #pragma unroll 1
    for (int i = 0; i < PER; i++) {
        int idx = base + i;
        if (idx < N_NODES) { g_rowptr[idx] = run; g_cursor[idx] = run; run += g_deg[idx]; }
    }
    if (tid == 0) g_rowptr[N_NODES] = N_EDGES;
}

__global__ void __launch_bounds__(256, 1)
k_scatter(const int* __restrict__ ei, const float* __restrict__ ev) {
    int e = blockIdx.x * blockDim.x + threadIdx.x;
    if (e < N_EDGES) {
        int dst = ei[e];
        int src = ei[N_EDGES + e];
        int pos = atomicAdd(&g_cursor[dst], 1);   // cursor pre-seeded with rowptr
        g_csr[pos] = make_uint2((unsigned)src, __float_as_uint(ev[e]));
    }
}

// ---------------------------------------------------------------------------
// HMMA GEMM: C[M,128](fp16) = A[M,K] @ B[K,128](fp16), fp32 accumulate
// TA = __half : cp.async double-buffered pipeline
// TA = float  : single-buffer, converts A fp32->fp16 while staging (GEMM1)
// 256 threads = 8 warps; block tile 128(M) x 128(N); warp tile 16 x 128
// ---------------------------------------------------------------------------
#define A_STRIDE 24    // halves per A smem row (16 + 8 pad)
#define B_STRIDE 136   // halves per B smem row (128 + 8 pad)
#define A_STAGE_BYTES (128 * A_STRIDE * 2)
#define B_STAGE_BYTES (16 * B_STRIDE * 2)

template <typename TA>
__global__ void __launch_bounds__(256)
k_gemm_hmma(const TA* __restrict__ A, const __half* __restrict__ B,
            __half* __restrict__ C, int M, int K) {
    __shared__ __half As[2][128 * A_STRIDE];
    __shared__ __half Bs[2][16 * B_STRIDE];

    const int tid  = threadIdx.x;
    const int warp = tid >> 5;
    const int lane = tid & 31;
    const int blockRow = blockIdx.x * 128;
    const int warpRow  = warp * 16;

    float c[16][4];
    #pragma unroll
    for (int j = 0; j < 16; j++)
        #pragma unroll
        for (int q = 0; q < 4; q++) c[j][q] = 0.f;

    // ldmatrix per-lane smem offsets (halves)
    const int aRow = warpRow + ((lane >> 3) & 1) * 8 + (lane & 7);
    const int aCol = (lane >> 4) * 8;
    const uint32_t aOffB = (uint32_t)(aRow * A_STRIDE + aCol) * 2;
    const int bRow  = ((lane >> 3) & 1) * 8 + (lane & 7);
    const int bColX = (lane >> 4) * 8;
    const uint32_t asBase = (uint32_t)__cvta_generic_to_shared(&As[0][0]);
    const uint32_t bsBase = (uint32_t)__cvta_generic_to_shared(&Bs[0][0]);

    // global load indices
    const int lar = tid >> 1,  lac = (tid & 1) * 8;   // A: 128 rows x 16 halves
    const int lbr = tid >> 4,  lbc = (tid & 15) * 8;  // B: 16 rows x 128 halves
    const int gra = blockRow + lar;
    const bool aValid = (gra < M);

    const int nTiles = K >> 4;

    if constexpr (is_half_t<TA>::value) {
        // ---- cp.async pipelined path ----
        const uint32_t aDst0 = asBase + (uint32_t)(lar * A_STRIDE + lac) * 2;
        const uint32_t bDst0 = bsBase + (uint32_t)(lbr * B_STRIDE + lbc) * 2;
        const int aSz = aValid ? 16 : 0;

        // prologue: tile 0 -> buf 0
        {
            const __half* aSrc = (const __half*)&A[(size_t)gra * K + lac];
            const __half* bSrc = &B[(size_t)lbr * 128 + lbc];
            asm volatile("cp.async.cg.shared.global [%0], [%1], 16, %2;"
                         :: "r"(aDst0), "l"(aSrc), "r"(aSz));
            asm volatile("cp.async.cg.shared.global [%0], [%1], 16;"
                         :: "r"(bDst0), "l"(bSrc));
            asm volatile("cp.async.commit_group;");
        }

        for (int t = 0; t < nTiles; t++) {
            const int buf = t & 1;
            if (t + 1 < nTiles) {
                const int k0 = (t + 1) << 4;
                const uint32_t aDst = aDst0 + (buf ^ 1) * A_STAGE_BYTES;
                const uint32_t bDst = bDst0 + (buf ^ 1) * B_STAGE_BYTES;
                const __half* aSrc = (const __half*)&A[(size_t)gra * K + k0 + lac];
                const __half* bSrc = &B[(size_t)(k0 + lbr) * 128 + lbc];
                asm volatile("cp.async.cg.shared.global [%0], [%1], 16, %2;"
                             :: "r"(aDst), "l"(aSrc), "r"(aSz));
                asm volatile("cp.async.cg.shared.global [%0], [%1], 16;"
                             :: "r"(bDst), "l"(bSrc));
                asm volatile("cp.async.commit_group;");
                asm volatile("cp.async.wait_group 1;");
            } else {
                asm volatile("cp.async.wait_group 0;");
            }
            __syncthreads();

            uint32_t aAddr = asBase + buf * A_STAGE_BYTES + aOffB;
            uint32_t a0, a1, a2, a3;
            asm volatile("ldmatrix.sync.aligned.m8n8.x4.shared.b16 {%0,%1,%2,%3}, [%4];"
                         : "=r"(a0), "=r"(a1), "=r"(a2), "=r"(a3) : "r"(aAddr));
            #pragma unroll
            for (int j = 0; j < 8; j++) {
                uint32_t bAddr = bsBase + buf * B_STAGE_BYTES +
                                 (uint32_t)(bRow * B_STRIDE + j * 16 + bColX) * 2;
                uint32_t b0, b1, b2, b3;
                asm volatile("ldmatrix.sync.aligned.m8n8.x4.trans.shared.b16 {%0,%1,%2,%3}, [%4];"
                             : "=r"(b0), "=r"(b1), "=r"(b2), "=r"(b3) : "r"(bAddr));
                asm volatile("mma.sync.aligned.m16n8k16.row.col.f32.f16.f16.f32 "
                             "{%0,%1,%2,%3},{%4,%5,%6,%7},{%8,%9},{%0,%1,%2,%3};"
                             : "+f"(c[2*j][0]), "+f"(c[2*j][1]), "+f"(c[2*j][2]), "+f"(c[2*j][3])
                             : "r"(a0), "r"(a1), "r"(a2), "r"(a3), "r"(b0), "r"(b1));
                asm volatile("mma.sync.aligned.m16n8k16.row.col.f32.f16.f16.f32 "
                             "{%0,%1,%2,%3},{%4,%5,%6,%7},{%8,%9},{%0,%1,%2,%3};"
                             : "+f"(c[2*j+1][0]), "+f"(c[2*j+1][1]), "+f"(c[2*j+1][2]), "+f"(c[2*j+1][3])
                             : "r"(a0), "r"(a1), "r"(a2), "r"(a3), "r"(b2), "r"(b3));
            }
            __syncthreads();
        }
    } else {
        // ---- fp32 A path (GEMM1): sync loads, convert while staging ----
        for (int t = 0; t < nTiles; t++) {
            const int k0 = t << 4;
            __half2 ah0 = __float2half2_rn(0.f), ah1 = ah0, ah2 = ah0, ah3 = ah0;
            if (aValid) {
                float4 v0 = *reinterpret_cast<const float4*>(&A[(size_t)gra * K + k0 + lac]);
                float4 v1 = *reinterpret_cast<const float4*>(&A[(size_t)gra * K + k0 + lac + 4]);
                ah0 = __floats2half2_rn(v0.x, v0.y);
                ah1 = __floats2half2_rn(v0.z, v0.w);
                ah2 = __floats2half2_rn(v1.x, v1.y);
                ah3 = __floats2half2_rn(v1.z, v1.w);
            }
            uint4 packed;
            packed.x = *reinterpret_cast<uint32_t*>(&ah0);
            packed.y = *reinterpret_cast<uint32_t*>(&ah1);
            packed.z = *reinterpret_cast<uint32_t*>(&ah2);
            packed.w = *reinterpret_cast<uint32_t*>(&ah3);
            *reinterpret_cast<uint4*>(&As[0][lar * A_STRIDE + lac]) = packed;
            *reinterpret_cast<uint4*>(&Bs[0][lbr * B_STRIDE + lbc]) =
                *reinterpret_cast<const uint4*>(&B[(size_t)(k0 + lbr) * 128 + lbc]);
            __syncthreads();

            uint32_t aAddr = asBase + aOffB;
            uint32_t a0, a1, a2, a3;
            asm volatile("ldmatrix.sync.aligned.m8n8.x4.shared.b16 {%0,%1,%2,%3}, [%4];"
                         : "=r"(a0), "=r"(a1), "=r"(a2), "=r"(a3) : "r"(aAddr));
            #pragma unroll
            for (int j = 0; j < 8; j++) {
                uint32_t bAddr = bsBase + (uint32_t)(bRow * B_STRIDE + j * 16 + bColX) * 2;
                uint32_t b0, b1, b2, b3;
                asm volatile("ldmatrix.sync.aligned.m8n8.x4.trans.shared.b16 {%0,%1,%2,%3}, [%4];"
                             : "=r"(b0), "=r"(b1), "=r"(b2), "=r"(b3) : "r"(bAddr));
                asm volatile("mma.sync.aligned.m16n8k16.row.col.f32.f16.f16.f32 "
                             "{%0,%1,%2,%3},{%4,%5,%6,%7},{%8,%9},{%0,%1,%2,%3};"
                             : "+f"(c[2*j][0]), "+f"(c[2*j][1]), "+f"(c[2*j][2]), "+f"(c[2*j][3])
                             : "r"(a0), "r"(a1), "r"(a2), "r"(a3), "r"(b0), "r"(b1));
                asm volatile("mma.sync.aligned.m16n8k16.row.col.f32.f16.f16.f32 "
                             "{%0,%1,%2,%3},{%4,%5,%6,%7},{%8,%9},{%0,%1,%2,%3};"
                             : "+f"(c[2*j+1][0]), "+f"(c[2*j+1][1]), "+f"(c[2*j+1][2]), "+f"(c[2*j+1][3])
                             : "r"(a0), "r"(a1), "r"(a2), "r"(a3), "r"(b2), "r"(b3));
            }
            __syncthreads();
        }
    }

    // epilogue: fp32 acc -> fp16 C
    const int row0 = blockRow + warpRow + (lane >> 2);
    const int row1 = row0 + 8;
    #pragma unroll
    for (int j = 0; j < 16; j++) {
        int col = j * 8 + (lane & 3) * 2;
        if (row0 < M) {
            __half2 p = __floats2half2_rn(c[j][0], c[j][1]);
            *reinterpret_cast<uint32_t*>(&C[(size_t)row0 * 128 + col]) =
                *reinterpret_cast<uint32_t*>(&p);
        }
        if (row1 < M) {
            __half2 p = __floats2half2_rn(c[j][2], c[j][3]);
            *reinterpret_cast<uint32_t*>(&C[(size_t)row1 * 128 + col]) =
                *reinterpret_cast<uint32_t*>(&p);
        }
    }
}

// ---------------------------------------------------------------------------
// SPMM (CSR gather, fp16 src, fp32 accum) + bias + ReLU
// ---------------------------------------------------------------------------
__global__ void __launch_bounds__(256, 4)
k_spmm(const __half* __restrict__ support,
       const float* __restrict__ bias,
       float* __restrict__ out32,        // may be null
       __half* __restrict__ out16) {
    int gw = (blockIdx.x * blockDim.x + threadIdx.x) >> 5;
    int lane = threadIdx.x & 31;
    if (gw >= N_NODES) return;

    int e   = g_rowptr[gw];
    int end = g_rowptr[gw + 1];

    float ax = 0.f, ay = 0.f, az = 0.f, aw = 0.f;
    const int off = lane * 4;

    for (; e + 4 <= end; e += 4) {
        #pragma unroll
        for (int u = 0; u < 4; u++) {
            uint2 cv = g_csr[e + u];
            float v = __uint_as_float(cv.y);
            uint2 raw = *reinterpret_cast<const uint2*>(&support[(size_t)cv.x * F + off]);
            float2 f0 = __half22float2(*reinterpret_cast<__half2*>(&raw.x));
            float2 f1 = __half22float2(*reinterpret_cast<__half2*>(&raw.y));
            ax = fmaf(v, f0.x, ax); ay = fmaf(v, f0.y, ay);
            az = fmaf(v, f1.x, az); aw = fmaf(v, f1.y, aw);
        }
    }
    for (; e < end; e++) {
        uint2 cv = g_csr[e];
        float v = __uint_as_float(cv.y);
        uint2 raw = *reinterpret_cast<const uint2*>(&support[(size_t)cv.x * F + off]);
        float2 f0 = __half22float2(*reinterpret_cast<__half2*>(&raw.x));
        float2 f1 = __half22float2(*reinterpret_cast<__half2*>(&raw.y));
        ax = fmaf(v, f0.x, ax); ay = fmaf(v, f0.y, ay);
        az = fmaf(v, f1.x, az); aw = fmaf(v, f1.y, aw);
    }

    float4 b = *reinterpret_cast<const float4*>(&bias[off]);
    ax = fmaxf(ax + b.x, 0.f); ay = fmaxf(ay + b.y, 0.f);
    az = fmaxf(az + b.z, 0.f); aw = fmaxf(aw + b.w, 0.f);

    if (out32)
        *reinterpret_cast<float4*>(&out32[(size_t)gw * F + off]) =
            make_float4(ax, ay, az, aw);

    __half2 p0 = __floats2half2_rn(ax, ay);
    __half2 p1 = __floats2half2_rn(az, aw);
    uint2 packed;
    packed.x = *reinterpret_cast<uint32_t*>(&p0);
    packed.y = *reinterpret_cast<uint32_t*>(&p1);
    *reinterpret_cast<uint2*>(&out16[(size_t)gw * F + off]) = packed;
}

// ---------------------------------------------------------------------------
extern "C" void kernel_launch(void* const* d_in, const int* in_sizes, int n_in,
                              void* d_out, int out_size) {
    const float* x  = (const float*)d_in[0];
    const int*   ei = (const int*)  d_in[1];
    const float* ev = (const float*)d_in[2];
    const float* W1 = (const float*)d_in[3];
    const float* b1 = (const float*)d_in[4];
    const float* W2 = (const float*)d_in[5];
    const float* b2 = (const float*)d_in[6];
    const float* W3 = (const float*)d_in[7];
    const float* b3 = (const float*)d_in[8];
    float* out = (float*)d_out;

    __half *support, *hh, *W1h, *W2h, *W3h;
    cudaGetSymbolAddress((void**)&support, g_support);
    cudaGetSymbolAddress((void**)&hh,      g_hh);
    cudaGetSymbolAddress((void**)&W1h,     g_W1h);
    cudaGetSymbolAddress((void**)&W2h,     g_W2h);
    cudaGetSymbolAddress((void**)&W3h,     g_W3h);

    // persistent side stream + events (created once; resources only, work is
    // identical every call)
    static cudaStream_t sSide = nullptr;
    static cudaEvent_t evFork = nullptr, evJoin = nullptr;
    if (!sSide) {
        cudaStreamCreateWithFlags(&sSide, cudaStreamNonBlocking);
        cudaEventCreateWithFlags(&evFork, cudaEventDisableTiming);
        cudaEventCreateWithFlags(&evJoin, cudaEventDisableTiming);
    }

    // fork: CSR build chain on side stream
    cudaEventRecord(evFork, 0);
    cudaStreamWaitEvent(sSide, evFork, 0);
    k_zero_counts<<<(N_NODES + 255) / 256, 256, 0, sSide>>>();
    k_hist<<<(N_EDGES + 255) / 256, 256, 0, sSide>>>(ei);
    k_scan<<<1, 1024, 0, sSide>>>();
    k_scatter<<<(N_EDGES + 255) / 256, 256, 0, sSide>>>(ei, ev);
    cudaEventRecord(evJoin, sSide);

    // main stream: weight conversions + GEMM1 (reads fp32 x directly)
    const int gemmGrid = (N_NODES + 127) / 128;
    const int spmmGrid = (N_NODES * 32 + 255) / 256;

    k_wconv<<<64, 256>>>(W1, W2, W3, W1h, W2h, W3h);
    k_gemm_hmma<float><<<gemmGrid, 256>>>(x, W1h, support, N_NODES, 256);

    // join: SPMM needs both GEMM1 (main) and CSR (side)
    cudaStreamWaitEvent(0, evJoin, 0);

    // layer 1: hh = relu(spmm(support) + b1)
    k_spmm<<<spmmGrid, 256>>>(support, b1, nullptr, hh);

    // layer 2: preds[0]
    k_gemm_hmma<__half><<<gemmGrid, 256>>>(hh, W2h, support, N_NODES, 128);
    k_spmm<<<spmmGrid, 256>>>(support, b2, out, hh);

    // timepoints 1..3
    for (int t = 1; t < T_POINTS; t++) {
        float* cur = out + (size_t)t * N_NODES * F;
        k_gemm_hmma<__half><<<gemmGrid, 256>>>(hh, W3h, support, N_NODES, 128);
        k_spmm<<<spmmGrid, 256>>>(support, b3, cur, hh);
    }
}

// round 7
// speedup vs baseline: 1.0105x; 1.0105x over previous
#include <cuda_runtime.h>
#include <cuda_fp16.h>
#include <stdint.h>

#define N_NODES 100000
#define N_EDGES 3200000
#define F 128
#define T_POINTS 4

// ---- scratch (device globals; no allocations allowed) ----
__device__ __half g_support[(size_t)N_NODES * F];  // GEMM out / SPMM gather src (25.6 MB)
__device__ __half g_hh[(size_t)N_NODES * F];       // layer output fp16 -> next GEMM A (25.6 MB)
__device__ __half g_W1h[256 * 128];
__device__ __half g_W2h[128 * 128];
__device__ __half g_W3h[128 * 128];
__device__ int    g_rowptr[N_NODES + 1];
__device__ int    g_deg[N_NODES];
__device__ int    g_cursor[N_NODES];
__device__ uint2  g_csr[N_EDGES];                  // {src col, val bits} (25.6 MB)

// minimal type trait (avoid C-only builtins / header deps)
template <typename T> struct is_half_t { static const bool value = false; };
template <> struct is_half_t<__half>  { static const bool value = true;  };

// ---------------------------------------------------------------------------
// all three weight matrices fp32 -> fp16 in one launch (65536 halves total)
// ---------------------------------------------------------------------------
__global__ void __launch_bounds__(256, 1)
k_wconv(const float* __restrict__ W1, const float* __restrict__ W2,
        const float* __restrict__ W3,
        __half* __restrict__ W1h, __half* __restrict__ W2h, __half* __restrict__ W3h) {
    int i4 = (blockIdx.x * blockDim.x + threadIdx.x) * 4;
    const float* src; __half* dst; int off;
    if (i4 < 32768)       { src = W1; dst = W1h; off = i4; }
    else if (i4 < 49152)  { src = W2; dst = W2h; off = i4 - 32768; }
    else                  { src = W3; dst = W3h; off = i4 - 49152; }
    float4 v = *reinterpret_cast<const float4*>(&src[off]);
    __half2 p0 = __floats2half2_rn(v.x, v.y);
    __half2 p1 = __floats2half2_rn(v.z, v.w);
    uint2 packed;
    packed.x = *reinterpret_cast<uint32_t*>(&p0);
    packed.y = *reinterpret_cast<uint32_t*>(&p1);
    *reinterpret_cast<uint2*>(&dst[off]) = packed;
}

// ---------------------------------------------------------------------------
// CSR build: histogram -> single-block scan -> scatter
// ---------------------------------------------------------------------------
__global__ void __launch_bounds__(256, 1) k_zero_counts() {
    int i = blockIdx.x * blockDim.x + threadIdx.x;
    if (i < N_NODES) g_deg[i] = 0;
}

__global__ void __launch_bounds__(256, 1) k_hist(const int* __restrict__ ei) {
    int e = blockIdx.x * blockDim.x + threadIdx.x;
    if (e < N_EDGES) atomicAdd(&g_deg[ei[e]], 1);
}

__global__ void __launch_bounds__(1024, 1) k_scan() {
    __shared__ int sums[1024];
    const int tid = threadIdx.x;
    const int PER = (N_NODES + 1023) / 1024;
    const int base = tid * PER;
    int s = 0;
    #pragma unroll 1
    for (int i = 0; i < PER; i++) {
        int idx = base + i;
        if (idx < N_NODES) s += g_deg[idx];
    }
    sums[tid] = s;
    __syncthreads();
    #pragma unroll 1
    for (int off = 1; off < 1024; off <<= 1) {
        int v = (tid >= off) ? sums[tid - off] : 0;
        __syncthreads();
        sums[tid] += v;
        __syncthreads();
    }
    int run = (tid == 0) ? 0 : sums[tid - 1];
    #pragma unroll 1
    for (int i = 0; i < PER; i++) {
        int idx = base + i;
        if (idx < N_NODES) { g_rowptr[idx] = run; g_cursor[idx] = run; run += g_deg[idx]; }
    }
    if (tid == 0) g_rowptr[N_NODES] = N_EDGES;
}

__global__ void __launch_bounds__(256, 1)
k_scatter(const int* __restrict__ ei, const float* __restrict__ ev) {
    int e = blockIdx.x * blockDim.x + threadIdx.x;
    if (e < N_EDGES) {
        int dst = ei[e];
        int src = ei[N_EDGES + e];
        int pos = atomicAdd(&g_cursor[dst], 1);   // cursor pre-seeded with rowptr
        g_csr[pos] = make_uint2((unsigned)src, __float_as_uint(ev[e]));
    }
}

// ---------------------------------------------------------------------------
// HMMA GEMM: C[M,128](fp16) = A[M,K] @ B[K,128](fp16), fp32 accumulate
// TA = __half : cp.async double-buffered pipeline
// TA = float  : single-buffer, converts A fp32->fp16 while staging (GEMM1)
// 256 threads = 8 warps; block tile 128(M) x 128(N); warp tile 16 x 128
// ---------------------------------------------------------------------------
#define A_STRIDE 24    // halves per A smem row (16 + 8 pad)
#define B_STRIDE 136   // halves per B smem row (128 + 8 pad)
#define A_STAGE_BYTES (128 * A_STRIDE * 2)
#define B_STAGE_BYTES (16 * B_STRIDE * 2)

template <typename TA>
__global__ void __launch_bounds__(256)
k_gemm_hmma(const TA* __restrict__ A, const __half* __restrict__ B,
            __half* __restrict__ C, int M, int K) {
    __shared__ __half As[2][128 * A_STRIDE];
    __shared__ __half Bs[2][16 * B_STRIDE];

    const int tid  = threadIdx.x;
    const int warp = tid >> 5;
    const int lane = tid & 31;
    const int blockRow = blockIdx.x * 128;
    const int warpRow  = warp * 16;

    float c[16][4];
    #pragma unroll
    for (int j = 0; j < 16; j++)
        #pragma unroll
        for (int q = 0; q < 4; q++) c[j][q] = 0.f;

    // ldmatrix per-lane smem offsets (halves)
    const int aRow = warpRow + ((lane >> 3) & 1) * 8 + (lane & 7);
    const int aCol = (lane >> 4) * 8;
    const uint32_t aOffB = (uint32_t)(aRow * A_STRIDE + aCol) * 2;
    const int bRow  = ((lane >> 3) & 1) * 8 + (lane & 7);
    const int bColX = (lane >> 4) * 8;
    const uint32_t asBase = (uint32_t)__cvta_generic_to_shared(&As[0][0]);
    const uint32_t bsBase = (uint32_t)__cvta_generic_to_shared(&Bs[0][0]);

    // global load indices
    const int lar = tid >> 1,  lac = (tid & 1) * 8;   // A: 128 rows x 16 halves
    const int lbr = tid >> 4,  lbc = (tid & 15) * 8;  // B: 16 rows x 128 halves
    const int gra = blockRow + lar;
    const bool aValid = (gra < M);

    const int nTiles = K >> 4;

    if constexpr (is_half_t<TA>::value) {
        // ---- cp.async pipelined path ----
        const uint32_t aDst0 = asBase + (uint32_t)(lar * A_STRIDE + lac) * 2;
        const uint32_t bDst0 = bsBase + (uint32_t)(lbr * B_STRIDE + lbc) * 2;
        const int aSz = aValid ? 16 : 0;

        // prologue: tile 0 -> buf 0
        {
            const __half* aSrc = (const __half*)&A[(size_t)gra * K + lac];
            const __half* bSrc = &B[(size_t)lbr * 128 + lbc];
            asm volatile("cp.async.cg.shared.global [%0], [%1], 16, %2;"
                         :: "r"(aDst0), "l"(aSrc), "r"(aSz));
            asm volatile("cp.async.cg.shared.global [%0], [%1], 16;"
                         :: "r"(bDst0), "l"(bSrc));
            asm volatile("cp.async.commit_group;");
        }

        for (int t = 0; t < nTiles; t++) {
            const int buf = t & 1;
            if (t + 1 < nTiles) {
                const int k0 = (t + 1) << 4;
                const uint32_t aDst = aDst0 + (buf ^ 1) * A_STAGE_BYTES;
                const uint32_t bDst = bDst0 + (buf ^ 1) * B_STAGE_BYTES;
                const __half* aSrc = (const __half*)&A[(size_t)gra * K + k0 + lac];
                const __half* bSrc = &B[(size_t)(k0 + lbr) * 128 + lbc];
                asm volatile("cp.async.cg.shared.global [%0], [%1], 16, %2;"
                             :: "r"(aDst), "l"(aSrc), "r"(aSz));
                asm volatile("cp.async.cg.shared.global [%0], [%1], 16;"
                             :: "r"(bDst), "l"(bSrc));
                asm volatile("cp.async.commit_group;");
                asm volatile("cp.async.wait_group 1;");
            } else {
                asm volatile("cp.async.wait_group 0;");
            }
            __syncthreads();

            uint32_t aAddr = asBase + buf * A_STAGE_BYTES + aOffB;
            uint32_t a0, a1, a2, a3;
            asm volatile("ldmatrix.sync.aligned.m8n8.x4.shared.b16 {%0,%1,%2,%3}, [%4];"
                         : "=r"(a0), "=r"(a1), "=r"(a2), "=r"(a3) : "r"(aAddr));
            #pragma unroll
            for (int j = 0; j < 8; j++) {
                uint32_t bAddr = bsBase + buf * B_STAGE_BYTES +
                                 (uint32_t)(bRow * B_STRIDE + j * 16 + bColX) * 2;
                uint32_t b0, b1, b2, b3;
                asm volatile("ldmatrix.sync.aligned.m8n8.x4.trans.shared.b16 {%0,%1,%2,%3}, [%4];"
                             : "=r"(b0), "=r"(b1), "=r"(b2), "=r"(b3) : "r"(bAddr));
                asm volatile("mma.sync.aligned.m16n8k16.row.col.f32.f16.f16.f32 "
                             "{%0,%1,%2,%3},{%4,%5,%6,%7},{%8,%9},{%0,%1,%2,%3};"
                             : "+f"(c[2*j][0]), "+f"(c[2*j][1]), "+f"(c[2*j][2]), "+f"(c[2*j][3])
                             : "r"(a0), "r"(a1), "r"(a2), "r"(a3), "r"(b0), "r"(b1));
                asm volatile("mma.sync.aligned.m16n8k16.row.col.f32.f16.f16.f32 "
                             "{%0,%1,%2,%3},{%4,%5,%6,%7},{%8,%9},{%0,%1,%2,%3};"
                             : "+f"(c[2*j+1][0]), "+f"(c[2*j+1][1]), "+f"(c[2*j+1][2]), "+f"(c[2*j+1][3])
                             : "r"(a0), "r"(a1), "r"(a2), "r"(a3), "r"(b2), "r"(b3));
            }
            __syncthreads();
        }
    } else {
        // ---- fp32 A path (GEMM1): sync loads, convert while staging ----
        for (int t = 0; t < nTiles; t++) {
            const int k0 = t << 4;
            __half2 ah0 = __float2half2_rn(0.f), ah1 = ah0, ah2 = ah0, ah3 = ah0;
            if (aValid) {
                float4 v0 = *reinterpret_cast<const float4*>(&A[(size_t)gra * K + k0 + lac]);
                float4 v1 = *reinterpret_cast<const float4*>(&A[(size_t)gra * K + k0 + lac + 4]);
                ah0 = __floats2half2_rn(v0.x, v0.y);
                ah1 = __floats2half2_rn(v0.z, v0.w);
                ah2 = __floats2half2_rn(v1.x, v1.y);
                ah3 = __floats2half2_rn(v1.z, v1.w);
            }
            uint4 packed;
            packed.x = *reinterpret_cast<uint32_t*>(&ah0);
            packed.y = *reinterpret_cast<uint32_t*>(&ah1);
            packed.z = *reinterpret_cast<uint32_t*>(&ah2);
            packed.w = *reinterpret_cast<uint32_t*>(&ah3);
            *reinterpret_cast<uint4*>(&As[0][lar * A_STRIDE + lac]) = packed;
            *reinterpret_cast<uint4*>(&Bs[0][lbr * B_STRIDE + lbc]) =
                *reinterpret_cast<const uint4*>(&B[(size_t)(k0 + lbr) * 128 + lbc]);
            __syncthreads();

            uint32_t aAddr = asBase + aOffB;
            uint32_t a0, a1, a2, a3;
            asm volatile("ldmatrix.sync.aligned.m8n8.x4.shared.b16 {%0,%1,%2,%3}, [%4];"
                         : "=r"(a0), "=r"(a1), "=r"(a2), "=r"(a3) : "r"(aAddr));
            #pragma unroll
            for (int j = 0; j < 8; j++) {
                uint32_t bAddr = bsBase + (uint32_t)(bRow * B_STRIDE + j * 16 + bColX) * 2;
                uint32_t b0, b1, b2, b3;
                asm volatile("ldmatrix.sync.aligned.m8n8.x4.trans.shared.b16 {%0,%1,%2,%3}, [%4];"
                             : "=r"(b0), "=r"(b1), "=r"(b2), "=r"(b3) : "r"(bAddr));
                asm volatile("mma.sync.aligned.m16n8k16.row.col.f32.f16.f16.f32 "
                             "{%0,%1,%2,%3},{%4,%5,%6,%7},{%8,%9},{%0,%1,%2,%3};"
                             : "+f"(c[2*j][0]), "+f"(c[2*j][1]), "+f"(c[2*j][2]), "+f"(c[2*j][3])
                             : "r"(a0), "r"(a1), "r"(a2), "r"(a3), "r"(b0), "r"(b1));
                asm volatile("mma.sync.aligned.m16n8k16.row.col.f32.f16.f16.f32 "
                             "{%0,%1,%2,%3},{%4,%5,%6,%7},{%8,%9},{%0,%1,%2,%3};"
                             : "+f"(c[2*j+1][0]), "+f"(c[2*j+1][1]), "+f"(c[2*j+1][2]), "+f"(c[2*j+1][3])
                             : "r"(a0), "r"(a1), "r"(a2), "r"(a3), "r"(b2), "r"(b3));
            }
            __syncthreads();
        }
    }

    // epilogue: fp32 acc -> fp16 C
    const int row0 = blockRow + warpRow + (lane >> 2);
    const int row1 = row0 + 8;
    #pragma unroll
    for (int j = 0; j < 16; j++) {
        int col = j * 8 + (lane & 3) * 2;
        if (row0 < M) {
            __half2 p = __floats2half2_rn(c[j][0], c[j][1]);
            *reinterpret_cast<uint32_t*>(&C[(size_t)row0 * 128 + col]) =
                *reinterpret_cast<uint32_t*>(&p);
        }
        if (row1 < M) {
            __half2 p = __floats2half2_rn(c[j][2], c[j][3]);
            *reinterpret_cast<uint32_t*>(&C[(size_t)row1 * 128 + col]) =
                *reinterpret_cast<uint32_t*>(&p);
        }
    }
}

// ---------------------------------------------------------------------------
// SPMM (CSR gather, fp16 src, fp32 accum) + bias + ReLU
// out32 / out16 independently optional (skip dead writes)
// ---------------------------------------------------------------------------
__global__ void __launch_bounds__(256, 4)
k_spmm(const __half* __restrict__ support,
       const float* __restrict__ bias,
       float* __restrict__ out32,        // may be null
       __half* __restrict__ out16) {     // may be null
    int gw = (blockIdx.x * blockDim.x + threadIdx.x) >> 5;
    int lane = threadIdx.x & 31;
    if (gw >= N_NODES) return;

    int e   = g_rowptr[gw];
    int end = g_rowptr[gw + 1];

    float ax = 0.f, ay = 0.f, az = 0.f, aw = 0.f;
    const int off = lane * 4;

    for (; e + 4 <= end; e += 4) {
        #pragma unroll
        for (int u = 0; u < 4; u++) {
            uint2 cv = g_csr[e + u];
            float v = __uint_as_float(cv.y);
            uint2 raw = *reinterpret_cast<const uint2*>(&support[(size_t)cv.x * F + off]);
            float2 f0 = __half22float2(*reinterpret_cast<__half2*>(&raw.x));
            float2 f1 = __half22float2(*reinterpret_cast<__half2*>(&raw.y));
            ax = fmaf(v, f0.x, ax); ay = fmaf(v, f0.y, ay);
            az = fmaf(v, f1.x, az); aw = fmaf(v, f1.y, aw);
        }
    }
    for (; e < end; e++) {
        uint2 cv = g_csr[e];
        float v = __uint_as_float(cv.y);
        uint2 raw = *reinterpret_cast<const uint2*>(&support[(size_t)cv.x * F + off]);
        float2 f0 = __half22float2(*reinterpret_cast<__half2*>(&raw.x));
        float2 f1 = __half22float2(*reinterpret_cast<__half2*>(&raw.y));
        ax = fmaf(v, f0.x, ax); ay = fmaf(v, f0.y, ay);
        az = fmaf(v, f1.x, az); aw = fmaf(v, f1.y, aw);
    }

    float4 b = *reinterpret_cast<const float4*>(&bias[off]);
    ax = fmaxf(ax + b.x, 0.f); ay = fmaxf(ay + b.y, 0.f);
    az = fmaxf(az + b.z, 0.f); aw = fmaxf(aw + b.w, 0.f);

    if (out32)
        *reinterpret_cast<float4*>(&out32[(size_t)gw * F + off]) =
            make_float4(ax, ay, az, aw);

    if (out16) {
        __half2 p0 = __floats2half2_rn(ax, ay);
        __half2 p1 = __floats2half2_rn(az, aw);
        uint2 packed;
        packed.x = *reinterpret_cast<uint32_t*>(&p0);
        packed.y = *reinterpret_cast<uint32_t*>(&p1);
        *reinterpret_cast<uint2*>(&out16[(size_t)gw * F + off]) = packed;
    }
}

// ---------------------------------------------------------------------------
extern "C" void kernel_launch(void* const* d_in, const int* in_sizes, int n_in,
                              void* d_out, int out_size) {
    const float* x  = (const float*)d_in[0];
    const int*   ei = (const int*)  d_in[1];
    const float* ev = (const float*)d_in[2];
    const float* W1 = (const float*)d_in[3];
    const float* b1 = (const float*)d_in[4];
    const float* W2 = (const float*)d_in[5];
    const float* b2 = (const float*)d_in[6];
    const float* W3 = (const float*)d_in[7];
    const float* b3 = (const float*)d_in[8];
    float* out = (float*)d_out;

    __half *support, *hh, *W1h, *W2h, *W3h;
    cudaGetSymbolAddress((void**)&support, g_support);
    cudaGetSymbolAddress((void**)&hh,      g_hh);
    cudaGetSymbolAddress((void**)&W1h,     g_W1h);
    cudaGetSymbolAddress((void**)&W2h,     g_W2h);
    cudaGetSymbolAddress((void**)&W3h,     g_W3h);

    const int gemmGrid = (N_NODES + 127) / 128;
    const int spmmGrid = (N_NODES * 32 + 255) / 256;

    // CSR build (sequential — concurrent execution with GEMM1 thrashes L2)
    k_zero_counts<<<(N_NODES + 255) / 256, 256>>>();
    k_hist<<<(N_EDGES + 255) / 256, 256>>>(ei);
    k_scan<<<1, 1024>>>();
    k_scatter<<<(N_EDGES + 255) / 256, 256>>>(ei, ev);

    // weight conversions + GEMM1 (reads fp32 x directly, converts in-register)
    k_wconv<<<64, 256>>>(W1, W2, W3, W1h, W2h, W3h);
    k_gemm_hmma<float><<<gemmGrid, 256>>>(x, W1h, support, N_NODES, 256);

    // layer 1: hh = relu(spmm(support) + b1)   (fp16 only — feeds GEMM 2)
    k_spmm<<<spmmGrid, 256>>>(support, b1, nullptr, hh);

    // layer 2: preds[0]
    k_gemm_hmma<__half><<<gemmGrid, 256>>>(hh, W2h, support, N_NODES, 128);
    k_spmm<<<spmmGrid, 256>>>(support, b2, out, hh);

    // timepoints 1..3 (last one: no fp16 copy needed)
    for (int t = 1; t < T_POINTS; t++) {
        float* cur = out + (size_t)t * N_NODES * F;
        k_gemm_hmma<__half><<<gemmGrid, 256>>>(hh, W3h, support, N_NODES, 128);
        k_spmm<<<spmmGrid, 256>>>(support, b3, cur,
                                  (t == T_POINTS - 1) ? nullptr : hh);
    }
}